// round 14
// baseline (speedup 1.0000x reference)
#include <cuda_runtime.h>
#include <cuda_fp16.h>
#include <stdint.h>
#include <math.h>

#define Bb 2
#define Hh 16
#define Ss 2048
#define Dd 64
#define BM 128          // q rows per CTA (16 per warp, 8 warps)
#define BN 64           // keys per tile
#define NTH 256
#define NKT (Ss / BN)   // 32
#define NELEM (Bb * Hh * Ss * Dd)   // 4194304
#define N4 (NELEM / 4)              // per-batch float4s = 2^19

// Pre-converted operands (device-global scratch; allocation-free per harness rules)
__device__ __half g_qhi[NELEM];
__device__ __half g_qlo[NELEM];
__device__ __half g_khi[NELEM];
__device__ __half g_klo[NELEM];
__device__ __half g_v[NELEM];

// SMEM layout (bytes). fp16 tiles, 144-byte row stride -> conflict-free ldmatrix.
#define RS 144
#define SM_QHI 0
#define SM_QLO (SM_QHI + BM * RS)        // 18432
#define SM_KHI (SM_QLO + BM * RS)        // 36864: 2 bufs x 9216
#define SM_KLO (SM_KHI + 2 * BN * RS)    // 55296
#define SM_V   (SM_KLO + 2 * BN * RS)    // 73728
#define SM_MASK (SM_V + 2 * BN * RS)     // 92160: 2 bufs x 256 B
#define SMEM_TOTAL (SM_MASK + 512)       // 92672 -> 2 CTAs/SM

__device__ __forceinline__ uint32_t smem_u32(const void* p) {
    uint32_t a;
    asm("{ .reg .u64 t; cvta.to.shared.u64 t, %1; cvt.u32.u64 %0, t; }" : "=r"(a) : "l"(p));
    return a;
}
#define CP16(dst, src) asm volatile("cp.async.cg.shared.global [%0], [%1], 16;" :: "r"(dst), "l"(src))
#define CP_COMMIT()    asm volatile("cp.async.commit_group;" ::: "memory")
#define CP_WAIT0()     asm volatile("cp.async.wait_group 0;" ::: "memory")

__device__ __forceinline__ void ldsm4(uint32_t* r, uint32_t a) {
    asm volatile("ldmatrix.sync.aligned.m8n8.x4.shared.b16 {%0,%1,%2,%3}, [%4];"
        : "=r"(r[0]), "=r"(r[1]), "=r"(r[2]), "=r"(r[3]) : "r"(a));
}
__device__ __forceinline__ void ldsm4t(uint32_t* r, uint32_t a) {
    asm volatile("ldmatrix.sync.aligned.m8n8.x4.trans.shared.b16 {%0,%1,%2,%3}, [%4];"
        : "=r"(r[0]), "=r"(r[1]), "=r"(r[2]), "=r"(r[3]) : "r"(a));
}
__device__ __forceinline__ void mma16816(float* d, const uint32_t* a, const uint32_t* b) {
    asm volatile("mma.sync.aligned.m16n8k16.row.col.f32.f16.f16.f32 "
        "{%0,%1,%2,%3}, {%4,%5,%6,%7}, {%8,%9}, {%0,%1,%2,%3};"
        : "+f"(d[0]), "+f"(d[1]), "+f"(d[2]), "+f"(d[3])
        : "r"(a[0]), "r"(a[1]), "r"(a[2]), "r"(a[3]), "r"(b[0]), "r"(b[1]));
}
__device__ __forceinline__ uint32_t cvth2(float a, float b) {   // a -> low half
    uint32_t r;
    asm("cvt.rn.f16x2.f32 %0, %1, %2;" : "=r"(r) : "f"(b), "f"(a));
    return r;
}
__device__ __forceinline__ float h2lo(uint32_t h) {
    return __half2float(__ushort_as_half((unsigned short)(h & 0xffffu)));
}
__device__ __forceinline__ float h2hi(uint32_t h) {
    return __half2float(__ushort_as_half((unsigned short)(h >> 16)));
}
__device__ __forceinline__ float ex2(float x) {   // single MUFU, no range-check code
    float r;
    asm("ex2.approx.f32 %0, %1;" : "=f"(r) : "f"(x));
    return r;
}

// ================= pre-pass: fp32 -> fp16 (hi/lo for Q,K; single for V) =================
__global__ __launch_bounds__(256) void prepass(
    const float* __restrict__ q, const float* __restrict__ k,
    const float* __restrict__ v, const float* __restrict__ sf)
{
    const int idx = blockIdx.x * 256 + threadIdx.x;   // float4 index
    const int job = blockIdx.y;
    if (job == 0) {
        float4 val = ((const float4*)q)[idx];
        const float s = sf[idx >> 19] * 1.4426950408889634f;   // fold log2(e)
        val.x *= s; val.y *= s; val.z *= s; val.w *= s;
        uint32_t h01 = cvth2(val.x, val.y), h23 = cvth2(val.z, val.w);
        ((uint2*)g_qhi)[idx] = make_uint2(h01, h23);
        ((uint2*)g_qlo)[idx] = make_uint2(cvth2(val.x - h2lo(h01), val.y - h2hi(h01)),
                                          cvth2(val.z - h2lo(h23), val.w - h2hi(h23)));
    } else if (job == 1) {
        float4 val = ((const float4*)k)[idx];
        uint32_t h01 = cvth2(val.x, val.y), h23 = cvth2(val.z, val.w);
        ((uint2*)g_khi)[idx] = make_uint2(h01, h23);
        ((uint2*)g_klo)[idx] = make_uint2(cvth2(val.x - h2lo(h01), val.y - h2hi(h01)),
                                          cvth2(val.z - h2lo(h23), val.w - h2hi(h23)));
    } else {
        float4 val = ((const float4*)v)[idx];
        ((uint2*)g_v)[idx] = make_uint2(cvth2(val.x, val.y), cvth2(val.z, val.w));
    }
}

// ================= main attention kernel =================
__global__ __launch_bounds__(NTH, 2) void attn_mma(
    const float* __restrict__ key_mask, float* __restrict__ out)
{
    extern __shared__ char smem[];
    const int tid = threadIdx.x;
    const int w   = tid >> 5;       // warp owns rows w*16..w*16+15
    const int lane = tid & 31;

    const int qt = blockIdx.x, bh = blockIdx.y, b = bh / Hh;
    const float* km = key_mask + (size_t)b * Ss;
    const char* qhp = (const char*)(g_qhi + ((size_t)bh * Ss + (size_t)qt * BM) * Dd);
    const char* qlp = (const char*)(g_qlo + ((size_t)bh * Ss + (size_t)qt * BM) * Dd);
    const char* kbh = (const char*)(g_khi + (size_t)bh * Ss * Dd);
    const char* kbl = (const char*)(g_klo + (size_t)bh * Ss * Dd);
    const char* vbp = (const char*)(g_v   + (size_t)bh * Ss * Dd);
    float* ob = out + ((size_t)bh * Ss + (size_t)qt * BM) * Dd;
    float* sMask = (float*)(smem + SM_MASK);
    const uint32_t sbase = smem_u32(smem);

    // ---- prologue: Q (hi+lo) and tile 0 (K hi/lo, V, mask) via cp.async ----
    for (int i = tid; i < BM * 8; i += NTH) {
        int r = i >> 3, c = i & 7;
        uint32_t off = r * RS + c * 16;
        CP16(sbase + SM_QHI + off, qhp + i * 16);
        CP16(sbase + SM_QLO + off, qlp + i * 16);
    }
    for (int i = tid; i < BN * 8; i += NTH) {
        int r = i >> 3, c = i & 7;
        uint32_t off = r * RS + c * 16;
        CP16(sbase + SM_KHI + off, kbh + i * 16);
        CP16(sbase + SM_KLO + off, kbl + i * 16);
        CP16(sbase + SM_V   + off, vbp + i * 16);
    }
    if (tid < 16) CP16(sbase + SM_MASK + tid * 16, (const char*)km + tid * 16);
    CP_COMMIT();
    CP_WAIT0();
    __syncthreads();

    // ldmatrix base addresses (per-lane)
    const uint32_t qaH = sbase + SM_QHI + (w * 16 + (lane & 15)) * RS + (lane >> 4) * 16;
    const uint32_t qaL = qaH + (SM_QLO - SM_QHI);
    const uint32_t ka0 = ((lane & 7) + ((lane >> 4) << 3)) * RS + (((lane >> 3) & 1) << 4);
    const uint32_t va0 = (lane & 15) * RS + ((lane >> 4) << 4);

    float oacc[8][4];
    float m_i[2], l_i[2];
    m_i[0] = m_i[1] = -INFINITY;
    l_i[0] = l_i[1] = 0.f;
    #pragma unroll
    for (int dt = 0; dt < 8; dt++)
        #pragma unroll
        for (int r = 0; r < 4; r++) oacc[dt][r] = 0.f;

    for (int kt = 0; kt < NKT; kt++) {
        const int buf = kt & 1;
        // ---- prefetch tile kt+1 into the other buffer (hidden behind compute) ----
        if (kt + 1 < NKT) {
            const size_t toff = (size_t)(kt + 1) * BN * Dd * 2;   // bytes (fp16)
            const uint32_t bo = (buf ^ 1) * BN * RS;
            for (int i = tid; i < BN * 8; i += NTH) {
                int r = i >> 3, c = i & 7;
                uint32_t off = bo + r * RS + c * 16;
                CP16(sbase + SM_KHI + off, kbh + toff + i * 16);
                CP16(sbase + SM_KLO + off, kbl + toff + i * 16);
                CP16(sbase + SM_V   + off, vbp + toff + i * 16);
            }
            if (tid < 16)
                CP16(sbase + SM_MASK + (buf ^ 1) * 256 + tid * 16,
                     (const char*)(km + (kt + 1) * BN) + tid * 16);
            CP_COMMIT();
        }
        const float* mk_tile = sMask + buf * 64;
        const uint32_t kaH = sbase + SM_KHI + buf * BN * RS + ka0;
        const uint32_t kaL = sbase + SM_KLO + buf * BN * RS + ka0;
        const uint32_t vaB = sbase + SM_V   + buf * BN * RS + va0;

        // ===== S = Qsplit @ Ksplit^T (3-term fp16 split, B-frag double-buffered) =====
        float sacc[8][4];
        #pragma unroll
        for (int nt = 0; nt < 8; nt++)
            #pragma unroll
            for (int r = 0; r < 4; r++) sacc[nt][r] = 0.f;

        uint32_t bH[2][4], bL[2][4];
        ldsm4(bH[0], kaH);          // (kc=0, pair p=0)
        ldsm4(bL[0], kaL);
        #pragma unroll
        for (int kc = 0; kc < 4; kc++) {
            uint32_t aH[4], aL[4];
            ldsm4(aH, qaH + kc * 32);
            ldsm4(aL, qaL + kc * 32);
            #pragma unroll
            for (int p = 0; p < 4; p++) {          // nt pair = 2p
                const int cur = p & 1;
                if (p < 3) {                        // preload next pair, same kc
                    ldsm4(bH[cur ^ 1], kaH + (2 * (p + 1)) * 8 * RS + kc * 32);
                    ldsm4(bL[cur ^ 1], kaL + (2 * (p + 1)) * 8 * RS + kc * 32);
                } else if (kc < 3) {                // preload first pair of next kc
                    ldsm4(bH[cur ^ 1], kaH + (kc + 1) * 32);
                    ldsm4(bL[cur ^ 1], kaL + (kc + 1) * 32);
                }
                const int nt = 2 * p;
                mma16816(sacc[nt],     aH, bH[cur]);
                mma16816(sacc[nt + 1], aH, bH[cur] + 2);
                mma16816(sacc[nt],     aL, bH[cur]);
                mma16816(sacc[nt + 1], aL, bH[cur] + 2);
                mma16816(sacc[nt],     aH, bL[cur]);
                mma16816(sacc[nt + 1], aH, bL[cur] + 2);
            }
        }

        // ===== online softmax (base-2, per row-slot h) =====
        float2 mkr[8];                  // mask cols for this thread (shared by both h)
        #pragma unroll
        for (int nt = 0; nt < 8; nt++)
            mkr[nt] = *(const float2*)&mk_tile[nt * 8 + 2 * (lane & 3)];

        float alpha[2];
        bool upd = false;
        #pragma unroll
        for (int h = 0; h < 2; h++) {
            const float mold = m_i[h];
            float mx = mold;
            #pragma unroll
            for (int nt = 0; nt < 8; nt++)
                mx = fmaxf(mx, fmaxf(sacc[nt][2 * h], sacc[nt][2 * h + 1]));
            mx = fmaxf(mx, __shfl_xor_sync(0xffffffffu, mx, 1));
            mx = fmaxf(mx, __shfl_xor_sync(0xffffffffu, mx, 2));
            alpha[h] = ex2(mold - mx);
            upd |= (mx > mold);
            m_i[h] = mx;

            float ls = 0.f;
            #pragma unroll
            for (int nt = 0; nt < 8; nt++) {
                float p0 = ex2(sacc[nt][2 * h]     - mx);
                float p1 = ex2(sacc[nt][2 * h + 1] - mx);
                ls += p0 + p1;                                // UNMASKED denominator
                sacc[nt][2 * h]     = p0 * mkr[nt].x;         // masked numerator
                sacc[nt][2 * h + 1] = p1 * mkr[nt].y;
            }
            ls += __shfl_xor_sync(0xffffffffu, ls, 1);
            ls += __shfl_xor_sync(0xffffffffu, ls, 2);
            l_i[h] = l_i[h] * alpha[h] + ls;
        }
        if (__any_sync(0xffffffffu, upd)) {   // sticky-max: rescale only when some row max rose
            #pragma unroll
            for (int dt = 0; dt < 8; dt++) {
                oacc[dt][0] *= alpha[0]; oacc[dt][1] *= alpha[0];
                oacc[dt][2] *= alpha[1]; oacc[dt][3] *= alpha[1];
            }
        }

        // ===== O += P(fp16) @ V(fp16)  (V-frag double-buffered) =====
        uint32_t bV[2][4];
        ldsm4t(bV[0], vaB);             // (kc=0, dt pair 0)
        #pragma unroll
        for (int kc = 0; kc < 4; kc++) {
            uint32_t pP[4];
            {
                const float* s0 = sacc[2 * kc];
                const float* s1 = sacc[2 * kc + 1];
                pP[0] = cvth2(s0[0], s0[1]); pP[1] = cvth2(s0[2], s0[3]);
                pP[2] = cvth2(s1[0], s1[1]); pP[3] = cvth2(s1[2], s1[3]);
            }
            #pragma unroll
            for (int p = 0; p < 4; p++) {           // dt pair = 2p
                const int cur = p & 1;
                if (p < 3) {
                    ldsm4t(bV[cur ^ 1], vaB + kc * 16 * RS + (2 * (p + 1)) * 16);
                } else if (kc < 3) {
                    ldsm4t(bV[cur ^ 1], vaB + (kc + 1) * 16 * RS);
                }
                const int dt = 2 * p;
                mma16816(oacc[dt],     pP, bV[cur]);
                mma16816(oacc[dt + 1], pP, bV[cur] + 2);
            }
        }

        // ---- make prefetched tile visible ----
        if (kt + 1 < NKT) {
            CP_WAIT0();
            __syncthreads();
        }
    }

    // ================= epilogue =================
    #pragma unroll
    for (int h = 0; h < 2; h++) {
        const float inv = 1.f / l_i[h];
        const int row = w * 16 + h * 8 + (lane >> 2);
        #pragma unroll
        for (int dt = 0; dt < 8; dt++) {
            float2 o;
            o.x = oacc[dt][2 * h]     * inv;
            o.y = oacc[dt][2 * h + 1] * inv;
            *(float2*)&ob[(size_t)row * Dd + dt * 8 + 2 * (lane & 3)] = o;
        }
    }
}

extern "C" void kernel_launch(void* const* d_in, const int* in_sizes, int n_in,
                              void* d_out, int out_size)
{
    const float* q  = (const float*)d_in[0];
    const float* k  = (const float*)d_in[1];
    const float* v  = (const float*)d_in[2];
    const float* km = (const float*)d_in[4];  // key_mask [B,1,1,S]
    const float* sf = (const float*)d_in[5];  // scale_factor [B]
    float* out = (float*)d_out;

    dim3 pgrid(N4 / 256, 3);
    prepass<<<pgrid, 256>>>(q, k, v, sf);

    cudaFuncSetAttribute(attn_mma, cudaFuncAttributeMaxDynamicSharedMemorySize, SMEM_TOTAL);
    dim3 grid(Ss / BM, Bb * Hh);   // 16 x 32
    attn_mma<<<grid, NTH, SMEM_TOTAL>>>(km, out);
}

// round 15
// speedup vs baseline: 1.0271x; 1.0271x over previous
#include <cuda_runtime.h>
#include <cuda_fp16.h>
#include <stdint.h>
#include <math.h>

#define Bb 2
#define Hh 16
#define Ss 2048
#define Dd 64
#define BM 128          // q rows per CTA (16 per warp, 8 warps)
#define BN 64           // keys per tile
#define NTH 256
#define NKT (Ss / BN)   // 32
#define NELEM (Bb * Hh * Ss * Dd)   // 4194304
#define N4 (NELEM / 4)              // per-batch float4s = 2^19

// Pre-converted operands (device-global scratch; allocation-free per harness rules)
__device__ __half g_qhi[NELEM];
__device__ __half g_qlo[NELEM];
__device__ __half g_khi[NELEM];
__device__ __half g_klo[NELEM];
__device__ __half g_v[NELEM];

// SMEM layout (bytes). fp16 tiles, 144-byte row stride -> conflict-free ldmatrix.
// K hi/lo double-buffered; V TRIPLE-buffered (PV runs one tile deferred).
#define RS 144
#define SM_QHI 0
#define SM_QLO (SM_QHI + BM * RS)        // 18432
#define SM_KHI (SM_QLO + BM * RS)        // 36864: 2 bufs x 9216
#define SM_KLO (SM_KHI + 2 * BN * RS)    // 55296: 2 bufs
#define SM_V   (SM_KLO + 2 * BN * RS)    // 73728: 3 bufs x 9216
#define SM_MASK (SM_V + 3 * BN * RS)     // 101376: 2 bufs x 256 B
#define SMEM_TOTAL (SM_MASK + 512)       // 101888 -> 2 CTAs/SM

__device__ __forceinline__ uint32_t smem_u32(const void* p) {
    uint32_t a;
    asm("{ .reg .u64 t; cvta.to.shared.u64 t, %1; cvt.u32.u64 %0, t; }" : "=r"(a) : "l"(p));
    return a;
}
#define CP16(dst, src) asm volatile("cp.async.cg.shared.global [%0], [%1], 16;" :: "r"(dst), "l"(src))
#define CP_COMMIT()    asm volatile("cp.async.commit_group;" ::: "memory")
#define CP_WAIT0()     asm volatile("cp.async.wait_group 0;" ::: "memory")

__device__ __forceinline__ void ldsm4(uint32_t* r, uint32_t a) {
    asm volatile("ldmatrix.sync.aligned.m8n8.x4.shared.b16 {%0,%1,%2,%3}, [%4];"
        : "=r"(r[0]), "=r"(r[1]), "=r"(r[2]), "=r"(r[3]) : "r"(a));
}
__device__ __forceinline__ void ldsm4t(uint32_t* r, uint32_t a) {
    asm volatile("ldmatrix.sync.aligned.m8n8.x4.trans.shared.b16 {%0,%1,%2,%3}, [%4];"
        : "=r"(r[0]), "=r"(r[1]), "=r"(r[2]), "=r"(r[3]) : "r"(a));
}
__device__ __forceinline__ void mma16816(float* d, const uint32_t* a, const uint32_t* b) {
    asm volatile("mma.sync.aligned.m16n8k16.row.col.f32.f16.f16.f32 "
        "{%0,%1,%2,%3}, {%4,%5,%6,%7}, {%8,%9}, {%0,%1,%2,%3};"
        : "+f"(d[0]), "+f"(d[1]), "+f"(d[2]), "+f"(d[3])
        : "r"(a[0]), "r"(a[1]), "r"(a[2]), "r"(a[3]), "r"(b[0]), "r"(b[1]));
}
__device__ __forceinline__ uint32_t cvth2(float a, float b) {   // a -> low half
    uint32_t r;
    asm("cvt.rn.f16x2.f32 %0, %1, %2;" : "=r"(r) : "f"(b), "f"(a));
    return r;
}
__device__ __forceinline__ float h2lo(uint32_t h) {
    return __half2float(__ushort_as_half((unsigned short)(h & 0xffffu)));
}
__device__ __forceinline__ float h2hi(uint32_t h) {
    return __half2float(__ushort_as_half((unsigned short)(h >> 16)));
}
__device__ __forceinline__ float ex2(float x) {
    float r;
    asm("ex2.approx.f32 %0, %1;" : "=f"(r) : "f"(x));
    return r;
}

// ================= pre-pass: fp32 -> fp16 (hi/lo for Q,K; single for V) =================
__global__ __launch_bounds__(256) void prepass(
    const float* __restrict__ q, const float* __restrict__ k,
    const float* __restrict__ v, const float* __restrict__ sf)
{
    const int idx = blockIdx.x * 256 + threadIdx.x;   // float4 index
    const int job = blockIdx.y;
    if (job == 0) {
        float4 val = ((const float4*)q)[idx];
        const float s = sf[idx >> 19] * 1.4426950408889634f;   // fold log2(e)
        val.x *= s; val.y *= s; val.z *= s; val.w *= s;
        uint32_t h01 = cvth2(val.x, val.y), h23 = cvth2(val.z, val.w);
        ((uint2*)g_qhi)[idx] = make_uint2(h01, h23);
        ((uint2*)g_qlo)[idx] = make_uint2(cvth2(val.x - h2lo(h01), val.y - h2hi(h01)),
                                          cvth2(val.z - h2lo(h23), val.w - h2hi(h23)));
    } else if (job == 1) {
        float4 val = ((const float4*)k)[idx];
        uint32_t h01 = cvth2(val.x, val.y), h23 = cvth2(val.z, val.w);
        ((uint2*)g_khi)[idx] = make_uint2(h01, h23);
        ((uint2*)g_klo)[idx] = make_uint2(cvth2(val.x - h2lo(h01), val.y - h2hi(h01)),
                                          cvth2(val.z - h2lo(h23), val.w - h2hi(h23)));
    } else {
        float4 val = ((const float4*)v)[idx];
        ((uint2*)g_v)[idx] = make_uint2(cvth2(val.x, val.y), cvth2(val.z, val.w));
    }
}

// ================= main attention kernel =================
__global__ __launch_bounds__(NTH, 2) void attn_mma(
    const float* __restrict__ key_mask, float* __restrict__ out)
{
    extern __shared__ char smem[];
    const int tid = threadIdx.x;
    const int w   = tid >> 5;       // warp owns rows w*16..w*16+15
    const int lane = tid & 31;

    const int qt = blockIdx.x, bh = blockIdx.y, b = bh / Hh;
    const float* km = key_mask + (size_t)b * Ss;
    const char* qhp = (const char*)(g_qhi + ((size_t)bh * Ss + (size_t)qt * BM) * Dd);
    const char* qlp = (const char*)(g_qlo + ((size_t)bh * Ss + (size_t)qt * BM) * Dd);
    const char* kbh = (const char*)(g_khi + (size_t)bh * Ss * Dd);
    const char* kbl = (const char*)(g_klo + (size_t)bh * Ss * Dd);
    const char* vbp = (const char*)(g_v   + (size_t)bh * Ss * Dd);
    float* ob = out + ((size_t)bh * Ss + (size_t)qt * BM) * Dd;
    float* sMask = (float*)(smem + SM_MASK);
    const uint32_t sbase = smem_u32(smem);

    // ---- prologue: Q (hi+lo) and tile 0 (K hi/lo -> buf0, V -> buf0, mask -> buf0) ----
    for (int i = tid; i < BM * 8; i += NTH) {
        int r = i >> 3, c = i & 7;
        uint32_t off = r * RS + c * 16;
        CP16(sbase + SM_QHI + off, qhp + i * 16);
        CP16(sbase + SM_QLO + off, qlp + i * 16);
    }
    for (int i = tid; i < BN * 8; i += NTH) {
        int r = i >> 3, c = i & 7;
        uint32_t off = r * RS + c * 16;
        CP16(sbase + SM_KHI + off, kbh + i * 16);
        CP16(sbase + SM_KLO + off, kbl + i * 16);
        CP16(sbase + SM_V   + off, vbp + i * 16);
    }
    if (tid < 16) CP16(sbase + SM_MASK + tid * 16, (const char*)km + tid * 16);
    CP_COMMIT();
    CP_WAIT0();
    __syncthreads();

    // ldmatrix base addresses (per-lane)
    const uint32_t qaH = sbase + SM_QHI + (w * 16 + (lane & 15)) * RS + (lane >> 4) * 16;
    const uint32_t qaL = qaH + (SM_QLO - SM_QHI);
    const uint32_t ka0 = ((lane & 7) + ((lane >> 4) << 3)) * RS + (((lane >> 3) & 1) << 4);
    const uint32_t va0 = (lane & 15) * RS + ((lane >> 4) << 4);

    float oacc[8][4];
    float m_i[2], l_i[2];
    uint32_t pP[4][4];      // packed masked-P of PREVIOUS tile (fp16x2), persists across iters
    m_i[0] = m_i[1] = -INFINITY;
    l_i[0] = l_i[1] = 0.f;
    #pragma unroll
    for (int dt = 0; dt < 8; dt++)
        #pragma unroll
        for (int r = 0; r < 4; r++) oacc[dt][r] = 0.f;

    for (int kt = 0; kt < NKT; kt++) {
        const int kbuf = kt & 1;

        // ===== (a) O += P(kt-1) @ V(kt-1)   [V buffer (kt-1) mod 3 — still valid] =====
        if (kt > 0) {
            const uint32_t vaB = sbase + SM_V + ((kt + 2) % 3) * (BN * RS) + va0;
            #pragma unroll
            for (int kc = 0; kc < 4; kc++) {
                #pragma unroll
                for (int dt = 0; dt < 8; dt += 2) {
                    uint32_t bV[4];
                    ldsm4t(bV, vaB + kc * 16 * RS + dt * 16);
                    mma16816(oacc[dt],     pP[kc], bV);
                    mma16816(oacc[dt + 1], pP[kc], bV + 2);
                }
            }
        }

        // ===== (b) prefetch tile kt+1 (K -> (kt+1)&1, V -> (kt+1)%3, mask -> (kt+1)&1) =====
        if (kt + 1 < NKT) {
            const size_t toff = (size_t)(kt + 1) * BN * Dd * 2;   // bytes (fp16)
            const uint32_t kbo = ((kt + 1) & 1) * (BN * RS);
            const uint32_t vbo = ((kt + 1) % 3) * (BN * RS);
            for (int i = tid; i < BN * 8; i += NTH) {
                int r = i >> 3, c = i & 7;
                uint32_t off = r * RS + c * 16;
                CP16(sbase + SM_KHI + kbo + off, kbh + toff + i * 16);
                CP16(sbase + SM_KLO + kbo + off, kbl + toff + i * 16);
                CP16(sbase + SM_V   + vbo + off, vbp + toff + i * 16);
            }
            if (tid < 16)
                CP16(sbase + SM_MASK + ((kt + 1) & 1) * 256 + tid * 16,
                     (const char*)(km + (kt + 1) * BN) + tid * 16);
            CP_COMMIT();
        }

        // ===== (c) S = Qsplit @ Ksplit^T (3-term fp16 split) =====
        const uint32_t kaH = sbase + SM_KHI + kbuf * (BN * RS) + ka0;
        const uint32_t kaL = sbase + SM_KLO + kbuf * (BN * RS) + ka0;
        float sacc[8][4];
        #pragma unroll
        for (int nt = 0; nt < 8; nt++)
            #pragma unroll
            for (int r = 0; r < 4; r++) sacc[nt][r] = 0.f;

        #pragma unroll
        for (int kc = 0; kc < 4; kc++) {
            uint32_t aH[4], aL[4];
            ldsm4(aH, qaH + kc * 32);
            ldsm4(aL, qaL + kc * 32);
            #pragma unroll
            for (int nt = 0; nt < 8; nt += 2) {
                uint32_t bH[4], bL[4];
                ldsm4(bH, kaH + nt * 8 * RS + kc * 32);
                ldsm4(bL, kaL + nt * 8 * RS + kc * 32);
                mma16816(sacc[nt],     aH, bH);
                mma16816(sacc[nt + 1], aH, bH + 2);
                mma16816(sacc[nt],     aL, bH);
                mma16816(sacc[nt + 1], aL, bH + 2);
                mma16816(sacc[nt],     aH, bL);
                mma16816(sacc[nt + 1], aH, bL + 2);
            }
        }

        // ===== (d) online softmax (base-2, per row-slot h) =====
        const float* mk_tile = sMask + kbuf * 64;
        #pragma unroll
        for (int h = 0; h < 2; h++) {
            const float mold = m_i[h];
            float mx = mold;
            #pragma unroll
            for (int nt = 0; nt < 8; nt++)
                mx = fmaxf(mx, fmaxf(sacc[nt][2 * h], sacc[nt][2 * h + 1]));
            mx = fmaxf(mx, __shfl_xor_sync(0xffffffffu, mx, 1));
            mx = fmaxf(mx, __shfl_xor_sync(0xffffffffu, mx, 2));
            const float alpha = ex2(mold - mx);   // 0 on first tile
            m_i[h] = mx;

            float ls = 0.f;
            #pragma unroll
            for (int nt = 0; nt < 8; nt++) {
                float p0 = ex2(sacc[nt][2 * h]     - mx);
                float p1 = ex2(sacc[nt][2 * h + 1] - mx);
                ls += p0 + p1;                                // UNMASKED denominator
                const float2 mk = *(const float2*)&mk_tile[nt * 8 + 2 * (lane & 3)];
                sacc[nt][2 * h]     = p0 * mk.x;              // masked numerator
                sacc[nt][2 * h + 1] = p1 * mk.y;
            }
            ls += __shfl_xor_sync(0xffffffffu, ls, 1);
            ls += __shfl_xor_sync(0xffffffffu, ls, 2);
            l_i[h] = l_i[h] * alpha + ls;

            // rescale O (scoreboard orders this after PV(kt-1) accumulation)
            #pragma unroll
            for (int dt = 0; dt < 8; dt++) {
                oacc[dt][2 * h]     *= alpha;
                oacc[dt][2 * h + 1] *= alpha;
            }
        }

        // ===== (e) pack masked P(kt) for next iteration's PV =====
        #pragma unroll
        for (int kc = 0; kc < 4; kc++) {
            const float* s0 = sacc[2 * kc];
            const float* s1 = sacc[2 * kc + 1];
            pP[kc][0] = cvth2(s0[0], s0[1]); pP[kc][1] = cvth2(s0[2], s0[3]);
            pP[kc][2] = cvth2(s1[0], s1[1]); pP[kc][3] = cvth2(s1[2], s1[3]);
        }

        // ===== (f) land prefetched tile =====
        if (kt + 1 < NKT) {
            CP_WAIT0();
            __syncthreads();
        }
    }

    // ===== tail: O += P(NKT-1) @ V(NKT-1) =====
    {
        const uint32_t vaB = sbase + SM_V + ((NKT - 1) % 3) * (BN * RS) + va0;
        #pragma unroll
        for (int kc = 0; kc < 4; kc++) {
            #pragma unroll
            for (int dt = 0; dt < 8; dt += 2) {
                uint32_t bV[4];
                ldsm4t(bV, vaB + kc * 16 * RS + dt * 16);
                mma16816(oacc[dt],     pP[kc], bV);
                mma16816(oacc[dt + 1], pP[kc], bV + 2);
            }
        }
    }

    // ================= epilogue =================
    #pragma unroll
    for (int h = 0; h < 2; h++) {
        const float inv = 1.f / l_i[h];
        const int row = w * 16 + h * 8 + (lane >> 2);
        #pragma unroll
        for (int dt = 0; dt < 8; dt++) {
            float2 o;
            o.x = oacc[dt][2 * h]     * inv;
            o.y = oacc[dt][2 * h + 1] * inv;
            *(float2*)&ob[(size_t)row * Dd + dt * 8 + 2 * (lane & 3)] = o;
        }
    }
}

extern "C" void kernel_launch(void* const* d_in, const int* in_sizes, int n_in,
                              void* d_out, int out_size)
{
    const float* q  = (const float*)d_in[0];
    const float* k  = (const float*)d_in[1];
    const float* v  = (const float*)d_in[2];
    const float* km = (const float*)d_in[4];  // key_mask [B,1,1,S]
    const float* sf = (const float*)d_in[5];  // scale_factor [B]
    float* out = (float*)d_out;

    dim3 pgrid(N4 / 256, 3);
    prepass<<<pgrid, 256>>>(q, k, v, sf);

    cudaFuncSetAttribute(attn_mma, cudaFuncAttributeMaxDynamicSharedMemorySize, SMEM_TOTAL);
    dim3 grid(Ss / BM, Bb * Hh);   // 16 x 32
    attn_mma<<<grid, NTH, SMEM_TOTAL>>>(km, out);
}

// round 17
// speedup vs baseline: 1.0375x; 1.0101x over previous
#include <cuda_runtime.h>
#include <cuda_fp16.h>
#include <stdint.h>
#include <math.h>

#define Bb 2
#define Hh 16
#define Ss 2048
#define Dd 64
#define BM 128          // q rows per CTA (16 per warp, 8 warps)
#define BN 64           // keys per tile
#define NTH 256
#define NKT (Ss / BN)   // 32
#define NELEM (Bb * Hh * Ss * Dd)   // 4194304
#define N4 (NELEM / 4)              // per-batch float4s = 2^19

// Pre-converted operands (device-global scratch; allocation-free per harness rules)
__device__ __half g_qhi[NELEM];
__device__ __half g_qlo[NELEM];
__device__ __half g_khi[NELEM];
__device__ __half g_klo[NELEM];
__device__ __half g_v[NELEM];
__device__ __half g_maskh[Bb * Ss];

// SMEM layout (bytes). fp16 tiles, 144-byte row stride -> conflict-free ldmatrix.
// Q_lo resident; K_hi/K_lo/V/mask in a 3-deep stage ring (mbarrier pipeline).
#define RS 144
#define SM_QLO 0
#define SM_STG (BM * RS)                 // 18432
#define TILEB (BN * RS)                  // 9216
#define KHOFF 0
#define KLOFF TILEB
#define VOFF  (2 * TILEB)
#define MKOFF (3 * TILEB)                // mask: 64 halfs = 128 B
#define STGSZ (3 * TILEB + 128)          // 27776
#define SM_BAR (SM_STG + 3 * STGSZ)      // 101760: full[3] @ +0, empty[3] @ +24
#define SMEM_TOTAL (SM_BAR + 128)        // 101888 -> 2 CTAs/SM

__device__ __forceinline__ uint32_t smem_u32(const void* p) {
    uint32_t a;
    asm("{ .reg .u64 t; cvta.to.shared.u64 t, %1; cvt.u32.u64 %0, t; }" : "=r"(a) : "l"(p));
    return a;
}
#define CP16(dst, src) asm volatile("cp.async.cg.shared.global [%0], [%1], 16;" :: "r"(dst), "l"(src))
#define CP_MBAR_ARRIVE(mb) asm volatile("cp.async.mbarrier.arrive.noinc.shared.b64 [%0];" :: "r"((uint32_t)(mb)) : "memory")
#define MBAR_INIT(mb, c) asm volatile("mbarrier.init.shared.b64 [%0], %1;" :: "r"((uint32_t)(mb)), "r"((uint32_t)(c)) : "memory")
#define MBAR_ARRIVE(mb) asm volatile("mbarrier.arrive.shared.b64 _, [%0];" :: "r"((uint32_t)(mb)) : "memory")
#define MBAR_WAIT(mb, ph) asm volatile("{\n\t.reg .pred P1;\n\tW_%=:\n\t" \
    "mbarrier.try_wait.parity.acquire.cta.shared::cta.b64 P1, [%0], %1, 0x989680;\n\t" \
    "@P1 bra.uni D_%=;\n\tbra.uni W_%=;\n\tD_%=:\n\t}" \
    :: "r"((uint32_t)(mb)), "r"((uint32_t)(ph)) : "memory")

__device__ __forceinline__ void ldsm4(uint32_t* r, uint32_t a) {
    asm volatile("ldmatrix.sync.aligned.m8n8.x4.shared.b16 {%0,%1,%2,%3}, [%4];"
        : "=r"(r[0]), "=r"(r[1]), "=r"(r[2]), "=r"(r[3]) : "r"(a));
}
__device__ __forceinline__ void ldsm4t(uint32_t* r, uint32_t a) {
    asm volatile("ldmatrix.sync.aligned.m8n8.x4.trans.shared.b16 {%0,%1,%2,%3}, [%4];"
        : "=r"(r[0]), "=r"(r[1]), "=r"(r[2]), "=r"(r[3]) : "r"(a));
}
__device__ __forceinline__ void mma16816(float* d, const uint32_t* a, const uint32_t* b) {
    asm volatile("mma.sync.aligned.m16n8k16.row.col.f32.f16.f16.f32 "
        "{%0,%1,%2,%3}, {%4,%5,%6,%7}, {%8,%9}, {%0,%1,%2,%3};"
        : "+f"(d[0]), "+f"(d[1]), "+f"(d[2]), "+f"(d[3])
        : "r"(a[0]), "r"(a[1]), "r"(a[2]), "r"(a[3]), "r"(b[0]), "r"(b[1]));
}
__device__ __forceinline__ uint32_t cvth2(float a, float b) {   // a -> low half
    uint32_t r;
    asm("cvt.rn.f16x2.f32 %0, %1, %2;" : "=r"(r) : "f"(b), "f"(a));
    return r;
}
__device__ __forceinline__ float h2lo(uint32_t h) {
    return __half2float(__ushort_as_half((unsigned short)(h & 0xffffu)));
}
__device__ __forceinline__ float h2hi(uint32_t h) {
    return __half2float(__ushort_as_half((unsigned short)(h >> 16)));
}
__device__ __forceinline__ float ex2(float x) {
    float r;
    asm("ex2.approx.f32 %0, %1;" : "=f"(r) : "f"(x));
    return r;
}

// ========= pre-pass: fp32 -> fp16 (hi/lo for Q,K; single for V; mask f16) =========
__global__ __launch_bounds__(256) void prepass(
    const float* __restrict__ q, const float* __restrict__ k,
    const float* __restrict__ v, const float* __restrict__ km,
    const float* __restrict__ sf)
{
    const int idx = blockIdx.x * 256 + threadIdx.x;   // float4 index
    const int job = blockIdx.y;
    if (job == 0) {
        float4 val = ((const float4*)q)[idx];
        const float s = sf[idx >> 19] * 1.4426950408889634f;   // fold log2(e)
        val.x *= s; val.y *= s; val.z *= s; val.w *= s;
        uint32_t h01 = cvth2(val.x, val.y), h23 = cvth2(val.z, val.w);
        ((uint2*)g_qhi)[idx] = make_uint2(h01, h23);
        ((uint2*)g_qlo)[idx] = make_uint2(cvth2(val.x - h2lo(h01), val.y - h2hi(h01)),
                                          cvth2(val.z - h2lo(h23), val.w - h2hi(h23)));
    } else if (job == 1) {
        float4 val = ((const float4*)k)[idx];
        uint32_t h01 = cvth2(val.x, val.y), h23 = cvth2(val.z, val.w);
        ((uint2*)g_khi)[idx] = make_uint2(h01, h23);
        ((uint2*)g_klo)[idx] = make_uint2(cvth2(val.x - h2lo(h01), val.y - h2hi(h01)),
                                          cvth2(val.z - h2lo(h23), val.w - h2hi(h23)));
    } else if (job == 2) {
        float4 val = ((const float4*)v)[idx];
        ((uint2*)g_v)[idx] = make_uint2(cvth2(val.x, val.y), cvth2(val.z, val.w));
    } else {
        if (idx < (Bb * Ss) / 4) {
            float4 m = ((const float4*)km)[idx];
            ((uint2*)g_maskh)[idx] = make_uint2(cvth2(m.x, m.y), cvth2(m.z, m.w));
        }
    }
}

// ================= main attention kernel =================
__global__ __launch_bounds__(NTH, 2) void attn_mma(float* __restrict__ out)
{
    extern __shared__ char smem[];
    const int tid = threadIdx.x;
    const int w   = tid >> 5;       // warp owns rows w*16..w*16+15
    const int lane = tid & 31;

    const int qt = blockIdx.x, bh = blockIdx.y, b = bh / Hh;
    const char* qlp = (const char*)(g_qlo + ((size_t)bh * Ss + (size_t)qt * BM) * Dd);
    const char* kbh = (const char*)(g_khi + (size_t)bh * Ss * Dd);
    const char* kbl = (const char*)(g_klo + (size_t)bh * Ss * Dd);
    const char* vbp = (const char*)(g_v   + (size_t)bh * Ss * Dd);
    const char* mbp = (const char*)(g_maskh + (size_t)b * Ss);
    float* ob = out + ((size_t)bh * Ss + (size_t)qt * BM) * Dd;
    const uint32_t sbase = smem_u32(smem);
    const uint32_t barF = sbase + SM_BAR;        // full[s] at +8s
    const uint32_t barE = sbase + SM_BAR + 24;   // empty[s] at +8s

    // ---- init barriers ----
    if (tid == 0) {
        #pragma unroll
        for (int s = 0; s < 3; s++) { MBAR_INIT(barF + 8 * s, NTH); MBAR_INIT(barE + 8 * s, NTH); }
    }
    __syncthreads();

    // ---- Q_hi fragments straight from gmem into registers (tile-invariant) ----
    uint32_t aH[4][4];
    {
        const uint32_t* qh = (const uint32_t*)g_qhi + ((size_t)bh * Ss + (size_t)qt * BM) * 32;
        const uint32_t* qr = qh + (size_t)(w * 16 + (lane >> 2)) * 32 + (lane & 3);
        #pragma unroll
        for (int kc = 0; kc < 4; kc++) {
            aH[kc][0] = qr[kc * 8];
            aH[kc][1] = qr[kc * 8 + 8 * 32];
            aH[kc][2] = qr[kc * 8 + 4];
            aH[kc][3] = qr[kc * 8 + 8 * 32 + 4];
        }
    }

    // ---- prologue: Q_lo + stages 0,1 via cp.async; completion via full[0]/full[1] ----
    for (int i = tid; i < BM * 8; i += NTH) {           // Q_lo
        int r = i >> 3, c = i & 7;
        CP16(sbase + SM_QLO + r * RS + c * 16, qlp + i * 16);
    }
    #pragma unroll
    for (int s = 0; s < 2; s++) {                       // stages 0,1 = tiles 0,1
        const size_t toff = (size_t)s * BN * Dd * 2;
        const uint32_t stg = sbase + SM_STG + s * STGSZ;
        for (int i = tid; i < BN * 8; i += NTH) {
            int r = i >> 3, c = i & 7;
            uint32_t off = r * RS + c * 16;
            CP16(stg + KHOFF + off, kbh + toff + i * 16);
            CP16(stg + KLOFF + off, kbl + toff + i * 16);
            CP16(stg + VOFF  + off, vbp + toff + i * 16);
        }
        if (tid < 8) CP16(stg + MKOFF + tid * 16, mbp + (size_t)s * BN * 2 + tid * 16);
        CP_MBAR_ARRIVE(barF + 8 * s);
    }

    // ldmatrix per-lane offsets (within a stage)
    const uint32_t qaL = sbase + SM_QLO + (w * 16 + (lane & 15)) * RS + (lane >> 4) * 16;
    const uint32_t ka0 = ((lane & 7) + ((lane >> 4) << 3)) * RS + (((lane >> 3) & 1) << 4);
    const uint32_t va0 = (lane & 15) * RS + ((lane >> 4) << 4);

    float oacc[8][4];
    float m_i[2], l_i[2];
    m_i[0] = m_i[1] = -INFINITY;
    l_i[0] = l_i[1] = 0.f;
    #pragma unroll
    for (int dt = 0; dt < 8; dt++)
        #pragma unroll
        for (int r = 0; r < 4; r++) oacc[dt][r] = 0.f;

    // pipeline counters: s = kt%3 (consume), p3 = (kt+2)%3 (produce)
    int s = 0, cons_par = 0;        // consumer full-parity = (kt/3)&1
    int p3 = 2, prod_par = 1;       // producer empty-parity = ((kt+2)/3 - 1)&1

    for (int kt = 0; kt < NKT; kt++) {
        // ===== producer: fill stage p3 for tile kt+2 =====
        if (kt + 2 < NKT) {
            MBAR_WAIT(barE + 8 * p3, prod_par);
            const size_t toff = (size_t)(kt + 2) * BN * Dd * 2;
            const uint32_t stg = sbase + SM_STG + p3 * STGSZ;
            for (int i = tid; i < BN * 8; i += NTH) {
                int r = i >> 3, c = i & 7;
                uint32_t off = r * RS + c * 16;
                CP16(stg + KHOFF + off, kbh + toff + i * 16);
                CP16(stg + KLOFF + off, kbl + toff + i * 16);
                CP16(stg + VOFF  + off, vbp + toff + i * 16);
            }
            if (tid < 8) CP16(stg + MKOFF + tid * 16, mbp + (size_t)(kt + 2) * BN * 2 + tid * 16);
            CP_MBAR_ARRIVE(barF + 8 * p3);
        }

        // ===== consumer: wait stage s ready =====
        MBAR_WAIT(barF + 8 * s, cons_par);
        const uint32_t stg = sbase + SM_STG + s * STGSZ;
        const uint32_t kaH = stg + KHOFF + ka0;
        const uint32_t kaL = stg + KLOFF + ka0;
        const uint32_t vaB = stg + VOFF + va0;

        // ----- S = Qsplit @ Ksplit^T (3-term fp16 split; Q_hi in regs) -----
        float sacc[8][4];
        #pragma unroll
        for (int nt = 0; nt < 8; nt++)
            #pragma unroll
            for (int r = 0; r < 4; r++) sacc[nt][r] = 0.f;

        #pragma unroll
        for (int kc = 0; kc < 4; kc++) {
            uint32_t aL[4];
            ldsm4(aL, qaL + kc * 32);
            #pragma unroll
            for (int nt = 0; nt < 8; nt += 2) {
                uint32_t bH[4], bL[4];
                ldsm4(bH, kaH + nt * 8 * RS + kc * 32);
                ldsm4(bL, kaL + nt * 8 * RS + kc * 32);
                mma16816(sacc[nt],     aH[kc], bH);
                mma16816(sacc[nt + 1], aH[kc], bH + 2);
                mma16816(sacc[nt],     aL,     bH);
                mma16816(sacc[nt + 1], aL,     bH + 2);
                mma16816(sacc[nt],     aH[kc], bL);
                mma16816(sacc[nt + 1], aH[kc], bL + 2);
            }
        }

        // ----- online softmax (base-2, f16x2 exp; masked product IS the P fragment) -----
        __half2 mk2[8];
        {
            const __half2* mks = (const __half2*)(smem + (stg - sbase) + MKOFF);
            #pragma unroll
            for (int nt = 0; nt < 8; nt++) mk2[nt] = mks[nt * 4 + (lane & 3)];
        }
        __half2 pP[4][4];
        bool upd = false;
        float alpha[2];
        #pragma unroll
        for (int h = 0; h < 2; h++) {
            const float mold = m_i[h];
            float mx = mold;
            #pragma unroll
            for (int nt = 0; nt < 8; nt++)
                mx = fmaxf(mx, fmaxf(sacc[nt][2 * h], sacc[nt][2 * h + 1]));
            mx = fmaxf(mx, __shfl_xor_sync(0xffffffffu, mx, 1));
            mx = fmaxf(mx, __shfl_xor_sync(0xffffffffu, mx, 2));
            alpha[h] = ex2(mold - mx);
            upd |= (mx > mold);
            m_i[h] = mx;

            float ls = 0.f;
            #pragma unroll
            for (int nt = 0; nt < 8; nt++) {
                __half2 lg = __floats2half2_rn(sacc[nt][2 * h] - mx, sacc[nt][2 * h + 1] - mx);
                __half2 pf = h2exp2(lg);
                float2 pp = __half22float2(pf);
                ls += pp.x + pp.y;                            // UNMASKED denominator
                pP[nt >> 1][(nt & 1) * 2 + h] = __hmul2(pf, mk2[nt]);   // masked numerator
            }
            ls += __shfl_xor_sync(0xffffffffu, ls, 1);
            ls += __shfl_xor_sync(0xffffffffu, ls, 2);
            l_i[h] = l_i[h] * alpha[h] + ls;
        }
        if (__any_sync(0xffffffffu, upd)) {
            #pragma unroll
            for (int dt = 0; dt < 8; dt++) {
                oacc[dt][0] *= alpha[0]; oacc[dt][1] *= alpha[0];
                oacc[dt][2] *= alpha[1]; oacc[dt][3] *= alpha[1];
            }
        }

        // ----- O += P(fp16) @ V(fp16) -----
        #pragma unroll
        for (int kc = 0; kc < 4; kc++) {
            const uint32_t* pPk = (const uint32_t*)pP[kc];
            #pragma unroll
            for (int dt = 0; dt < 8; dt += 2) {
                uint32_t bV[4];
                ldsm4t(bV, vaB + kc * 16 * RS + dt * 16);
                mma16816(oacc[dt],     pPk, bV);
                mma16816(oacc[dt + 1], pPk, bV + 2);
            }
        }

        // ===== done reading stage s =====
        MBAR_ARRIVE(barE + 8 * s);

        // advance pipeline counters
        s++;  if (s == 3)  { s = 0;  cons_par ^= 1; }
        p3++; if (p3 == 3) { p3 = 0; prod_par ^= 1; }
    }

    // ================= epilogue =================
    #pragma unroll
    for (int h = 0; h < 2; h++) {
        const float inv = 1.f / l_i[h];
        const int row = w * 16 + h * 8 + (lane >> 2);
        #pragma unroll
        for (int dt = 0; dt < 8; dt++) {
            float2 o;
            o.x = oacc[dt][2 * h]     * inv;
            o.y = oacc[dt][2 * h + 1] * inv;
            *(float2*)&ob[(size_t)row * Dd + dt * 8 + 2 * (lane & 3)] = o;
        }
    }
}

extern "C" void kernel_launch(void* const* d_in, const int* in_sizes, int n_in,
                              void* d_out, int out_size)
{
    const float* q  = (const float*)d_in[0];
    const float* k  = (const float*)d_in[1];
    const float* v  = (const float*)d_in[2];
    const float* km = (const float*)d_in[4];  // key_mask [B,1,1,S]
    const float* sf = (const float*)d_in[5];  // scale_factor [B]
    float* out = (float*)d_out;

    dim3 pgrid(N4 / 256, 4);
    prepass<<<pgrid, 256>>>(q, k, v, km, sf);

    cudaFuncSetAttribute(attn_mma, cudaFuncAttributeMaxDynamicSharedMemorySize, SMEM_TOTAL);
    dim3 grid(Ss / BM, Bb * Hh);   // 16 x 32
    attn_mma<<<grid, NTH, SMEM_TOTAL>>>(out);
}